// round 1
// baseline (speedup 1.0000x reference)
#include <cuda_runtime.h>

// Problem constants
#define BB 16
#define CC_TOT 256
#define HH 48
#define WW 48
#define H1 24
#define W1 24
#define ND 9            // displacement count per axis
#define IT 2            // output rows per CTA
#define NIG 12          // i-groups (24 / IT)
#define CSPLIT 2        // channel split across CTAs
#define CCH 16          // channels per smem chunk
#define NCHUNK ((CC_TOT/CSPLIT)/CCH)  // 8
#define NCG 8           // channel groups (warpsets) inside CTA
#define LPG 56          // lanes per group (54 active + 2 idle)
#define NTHREADS (NCG*LPG)   // 448
#define TJ 8            // j-block per thread
#define NROWS (IT + ND - 1)  // 10 x2 rows needed
#define XS 36           // padded smem row stride (floats, 16B-multiple)
#define NLANES 54       // 9 q * 3 jb * 2 ii

// partial sums: [CSPLIT][B*NIG][NLANES*72]
__device__ float g_partial[(size_t)CSPLIT * BB * NIG * NLANES * 72];

__global__ __launch_bounds__(NTHREADS, 1)
void corr_kernel(const float* __restrict__ x1, const float* __restrict__ x2)
{
    __shared__ __align__(16) float x2s[CCH][NROWS][XS];  // 23040 B
    __shared__ __align__(16) float x1s[CCH][IT][W1];     //  3072 B

    const int ig  = blockIdx.x;      // 0..11
    const int b   = blockIdx.y;      // 0..15
    const int cs  = blockIdx.z;      // 0..1
    const int i0  = ig * IT;
    const int tid = threadIdx.x;
    const int g   = tid / LPG;       // 0..7
    const int r   = tid % LPG;       // 0..55
    const bool act = (r < NLANES);
    const int q   = r % 9;
    const int jb  = (r / 9) % 3;
    const int ii  = (r < NLANES) ? (r / 27) : 0;   // 0..1

    const int c_base = cs * (CC_TOT / CSPLIT);

    const float* __restrict__ x2b = x2 + (size_t)b * CC_TOT * (HH * WW);
    const float* __restrict__ x1b = x1 + (size_t)b * CC_TOT * (HH * WW);

    float pf2[9];
    float pf1[2];

    auto load_chunk = [&](int chunk) {
        const int c0 = c_base + chunk * CCH;
        #pragma unroll
        for (int t = 0; t < 9; ++t) {
            int idx = tid + t * NTHREADS;
            float v = 0.f;
            if (idx < CCH * NROWS * W1) {
                int ix = idx % W1;
                int rr = (idx / W1) % NROWS;
                int cc = idx / (W1 * NROWS);
                int iy = i0 - 4 + rr;
                if (iy >= 0 && iy < H1)
                    v = x2b[((size_t)(c0 + cc) * HH + 2 * iy) * WW + 2 * ix];
            }
            pf2[t] = v;
        }
        #pragma unroll
        for (int t = 0; t < 2; ++t) {
            int idx = tid + t * NTHREADS;
            float v = 0.f;
            if (idx < CCH * IT * W1) {
                int j  = idx % W1;
                int iw = (idx / W1) % IT;
                int cc = idx / (W1 * IT);
                v = x1b[((size_t)(c0 + cc) * HH + 2 * (i0 + iw)) * WW + 2 * j];
            }
            pf1[t] = v;
        }
    };

    auto store_chunk = [&]() {
        #pragma unroll
        for (int t = 0; t < 9; ++t) {
            int idx = tid + t * NTHREADS;
            if (idx < CCH * NROWS * W1) {
                int ix = idx % W1;
                int rr = (idx / W1) % NROWS;
                int cc = idx / (W1 * NROWS);
                x2s[cc][rr][4 + ix] = pf2[t];
            }
        }
        #pragma unroll
        for (int t = 0; t < 2; ++t) {
            int idx = tid + t * NTHREADS;
            if (idx < CCH * IT * W1) {
                int j  = idx % W1;
                int iw = (idx / W1) % IT;
                int cc = idx / (W1 * IT);
                x1s[cc][iw][j] = pf1[t];
            }
        }
    };

    // one-time zero of x2s (padding columns / OOB rows stay zero forever)
    for (int idx = tid; idx < CCH * NROWS * XS; idx += NTHREADS)
        (&x2s[0][0][0])[idx] = 0.f;

    load_chunk(0);
    __syncthreads();   // zero-init visible before interior stores

    float acc[72];
    #pragma unroll
    for (int k = 0; k < 72; ++k) acc[k] = 0.f;

    for (int chunk = 0; chunk < NCHUNK; ++chunk) {
        store_chunk();
        __syncthreads();
        if (chunk + 1 < NCHUNK) load_chunk(chunk + 1);  // prefetch overlaps compute

        if (act) {
            #pragma unroll
            for (int c4 = 0; c4 < CCH / NCG; ++c4) {
                const int cc = g * (CCH / NCG) + c4;
                const float* xw = &x2s[cc][ii + q][jb * TJ];
                const float* xv = &x1s[cc][ii][jb * TJ];
                float w[16], f[8];
                #pragma unroll
                for (int t4 = 0; t4 < 4; ++t4) {
                    float4 v = *reinterpret_cast<const float4*>(xw + t4 * 4);
                    w[t4*4+0] = v.x; w[t4*4+1] = v.y; w[t4*4+2] = v.z; w[t4*4+3] = v.w;
                }
                #pragma unroll
                for (int t4 = 0; t4 < 2; ++t4) {
                    float4 v = *reinterpret_cast<const float4*>(xv + t4 * 4);
                    f[t4*4+0] = v.x; f[t4*4+1] = v.y; f[t4*4+2] = v.z; f[t4*4+3] = v.w;
                }
                #pragma unroll
                for (int jj = 0; jj < 8; ++jj) {
                    #pragma unroll
                    for (int p = 0; p < 9; ++p)
                        acc[jj * 9 + p] += f[jj] * w[jj + p];
                }
            }
        }
        __syncthreads();
    }

    // reduce across the 8 channel-groups into group 0 (buf aliases x2s)
    float (*buf)[73] = reinterpret_cast<float(*)[73]>(&x2s[0][0][0]);
    #pragma unroll 1
    for (int src = 1; src < NCG; ++src) {
        if (g == src && act) {
            #pragma unroll
            for (int k = 0; k < 72; ++k) buf[r][k] = acc[k];
        }
        __syncthreads();
        if (g == 0 && act) {
            #pragma unroll
            for (int k = 0; k < 72; ++k) acc[k] += buf[r][k];
        }
        __syncthreads();
    }
    if (g == 0 && act) {
        #pragma unroll
        for (int k = 0; k < 72; ++k) buf[r][k] = acc[k];
    }
    __syncthreads();

    float* dst = g_partial +
                 ((size_t)cs * (BB * NIG) + (size_t)b * NIG + ig) * (NLANES * 72);
    for (int idx = tid; idx < NLANES * 72; idx += NTHREADS)
        dst[idx] = buf[idx / 72][idx % 72];
}

__global__ void finalize_kernel(float* __restrict__ out)
{
    int idx = blockIdx.x * blockDim.x + threadIdx.x;
    if (idx >= BB * 81 * H1 * W1) return;
    int j  = idx % W1;
    int i  = (idx / W1) % H1;
    int qp = (idx / (W1 * H1)) % 81;
    int b  = idx / (W1 * H1 * 81);

    int ig = i / IT, iw = i % IT;
    int q  = qp / 9, p = qp % 9;
    int jbv = j / TJ, jj = j % TJ;
    int r  = iw * 27 + jbv * 9 + q;
    int k  = jj * 9 + p;

    size_t base = ((size_t)b * NIG + ig) * (NLANES * 72) + (size_t)r * 72 + k;
    size_t half = (size_t)(BB * NIG) * (NLANES * 72);
    out[idx] = (g_partial[base] + g_partial[half + base]) * (1.0f / 256.0f);
}

extern "C" void kernel_launch(void* const* d_in, const int* in_sizes, int n_in,
                              void* d_out, int out_size)
{
    const float* x1 = (const float*)d_in[0];
    const float* x2 = (const float*)d_in[1];
    float* out = (float*)d_out;

    dim3 grid(NIG, BB, CSPLIT);
    corr_kernel<<<grid, NTHREADS>>>(x1, x2);

    int total = BB * 81 * H1 * W1;           // 746496 = 1458 * 512
    finalize_kernel<<<(total + 511) / 512, 512>>>(out);
}